// round 16
// baseline (speedup 1.0000x reference)
#include <cuda_runtime.h>
#include <math.h>

#define W 384
#define H 384
#define HW (W*H)
#define NIMG 24

#define TAU 3e-4f

// ---------------- scratch (no allocations allowed) ----------------
__device__ float g_bp[3][NIMG*HW];        // bandpasses

// =====================================================================
// Compile-time double-precision math (matches numpy float64 to ~1e-15)
// =====================================================================
constexpr double PI_ = 3.14159265358979323846264338327950288;

constexpr double cexp(double x) {
    const double LN2 = 0.69314718055994530941723212145817657;
    int n = (int)(x / LN2 + (x >= 0 ? 0.5 : -0.5));
    double r = x - (double)n * LN2;
    double t = 1.0, term = 1.0;
    for (int i = 1; i <= 22; i++) { term *= r / (double)i; t += term; }
    double s = 1.0;
    if (n >= 0) for (int i = 0; i < n; i++)  s *= 2.0;
    else        for (int i = 0; i < -n; i++) s *= 0.5;
    return t * s;
}
constexpr double ccos(double x) {
    double t = x; bool neg = false;
    if (t > PI_ * 0.5) { t = PI_ - t; neg = true; }
    double t2 = t*t, term = 1.0, s = 1.0;
    for (int i = 1; i <= 16; i++) { term *= -t2 / (double)((2*i-1)*(2*i)); s += term; }
    return neg ? -s : s;
}
constexpr double csin(double x) {
    double t = x;
    if (t > PI_ * 0.5) t = PI_ - t;
    double t2 = t*t, term = t, s = t;
    for (int i = 1; i <= 16; i++) { term *= -t2 / (double)((2*i)*(2*i+1)); s += term; }
    return s;
}
constexpr double csqrt(double x) {
    if (x <= 0.0) return 0.0;
    double y = (x > 1.0) ? x : 1.0;
    for (int i = 0; i < 80; i++) y = 0.5 * (y + x / y);
    return y;
}

// ---------------- oriented 15x15 filters, computed at compile time ----------------
struct F225 { float w[225]; };

constexpr F225 make_filt(int s, int d, int nd) {
    double scale = (double)(s + 1);
    double sx = 2.0 * scale, sy = 0.5 * scale;
    double ang = PI_ * (double)d / (double)nd;
    double ca = ccos(ang), sa = csin(ang);
    double k[225] = {};
    double sum = 0.0;
    for (int i = 0; i < 15; i++) {
        for (int j = 0; j < 15; j++) {
            double X = (double)(j - 7), Y = (double)(i - 7);
            double Xr = X * ca - Y * sa;
            double Yr = X * sa + Y * ca;
            double v = cexp(-0.5 * (Xr*Xr/(sx*sx) + Yr*Yr/(sy*sy))) * Xr / (sx*sx);
            k[i*15 + j] = v;
            sum += v;
        }
    }
    double mean = sum / 225.0;
    double nr = 0.0;
    for (int i = 0; i < 225; i++) { k[i] -= mean; nr += k[i]*k[i]; }
    nr = csqrt(nr);
    double inv = (nr > 1e-6) ? 1.0 / nr : 1.0;
    F225 f{};
    for (int i = 0; i < 225; i++) f.w[i] = (float)(k[i] * inv);
    return f;
}

template<int S, int D, int ND>
struct Filt { static constexpr F225 f = make_filt(S, D, ND); };
template<int S, int D, int ND> constexpr F225 Filt<S, D, ND>::f;

// ---------------- separable 5-tap gaussian at compile time ----------------
struct F5 { float h[5]; float v[5]; };
constexpr F5 make_k1() {
    double g[5] = {}; double s1 = 0.0;
    for (int i = 0; i < 5; i++) { double a = (double)(i - 2); g[i] = cexp(-0.5*a*a); s1 += g[i]; }
    double k1[5] = {};
    for (int i = 0; i < 5; i++) k1[i] = g[i] / s1;
    double s2 = 0.0;
    for (int i = 0; i < 5; i++)
        for (int j = 0; j < 5; j++) s2 += k1[i]*k1[j];
    F5 f{};
    for (int i = 0; i < 5; i++) { f.h[i] = (float)k1[i]; f.v[i] = (float)(k1[i] / s2); }
    return f;
}
template<int DUMMY>
struct K1T { static constexpr F5 f = make_k1(); };
template<int DUMMY> constexpr F5 K1T<DUMMY>::f;

__device__ __forceinline__ int reflect_idx(int i, int n) {
    if (i < 0) return -i;
    if (i >= n) return 2*n - 2 - i;
    return i;
}

__device__ __forceinline__ float fsub_fma(float a, float b) {
    return fmaf(b, -1.0f, a);
}

// 5-tap horiz / vert with immediate weights
template<int I>
struct H5t {
    static __device__ __forceinline__ void run(const float* s, float& a) {
        constexpr float w = K1T<0>::f.h[I];
        a = fmaf(s[I], w, a);
        H5t<I+1>::run(s, a);
    }
};
template<> struct H5t<5> { static __device__ __forceinline__ void run(const float*, float&) {} };
__device__ __forceinline__ float h5(const float* s) { float a = 0.f; H5t<0>::run(s, a); return a; }

template<int STR, int I>
struct V5t {
    static __device__ __forceinline__ void run(const float* s, float& a) {
        constexpr float w = K1T<0>::f.v[I];
        a = fmaf(s[I*STR], w, a);
        V5t<STR, I+1>::run(s, a);
    }
};
template<int STR> struct V5t<STR, 5> { static __device__ __forceinline__ void run(const float*, float&) {} };
template<int STR>
__device__ __forceinline__ float v5(const float* s) { float a = 0.f; V5t<STR,0>::run(s, a); return a; }

// =====================================================================
// Fused 3-stage Laplacian pyramid, separable 5-tap passes.
// =====================================================================
#define B0S 76

__global__ __launch_bounds__(256) void lp_fused_kernel(const float* __restrict__ xin,
                                                       float* __restrict__ dout) {
    __shared__ float b0[28 * B0S];
    __shared__ float t1[28 * 72];
    __shared__ float b1[24 * 72];
    __shared__ float t2[24 * 68];
    __shared__ float b2[20 * 68];
    __shared__ float t3[20 * 64];

    int img = blockIdx.z;
    int x0 = blockIdx.x * 64;
    int y0 = blockIdx.y * 16;
    const float* base = xin + (size_t)img * HW;
    int tid = threadIdx.x;

    for (int i = tid; i < 28 * B0S; i += 256) {
        int r = i / B0S, c = i - r * B0S;
        int gy = reflect_idx(y0 - 6 + r, H);
        int gx = reflect_idx(x0 - 6 + c, W);
        b0[i] = __ldg(base + gy * W + gx);
    }
    __syncthreads();

    for (int i = tid; i < 28 * 72; i += 256) {
        int r = i / 72, c = i - r * 72;
        t1[i] = h5(&b0[r * B0S + c]);
    }
    __syncthreads();
    for (int i = tid; i < 24 * 72; i += 256) {
        int r = i / 72, c = i - r * 72;
        b1[i] = v5<72>(&t1[r * 72 + c]);
    }
    __syncthreads();

    size_t pbase = (size_t)img * HW;
    {
        int i = tid;
        int ty = i >> 4, tx4 = (i & 15) * 4;
        float v[4];
        #pragma unroll
        for (int t = 0; t < 4; t++)
            v[t] = b0[(ty+6)*B0S + tx4 + t + 6] - b1[(ty+4)*72 + tx4 + t + 4];
        *(float4*)&g_bp[0][pbase + (size_t)(y0+ty)*W + x0 + tx4] =
            make_float4(v[0], v[1], v[2], v[3]);
    }
    for (int i = tid; i < 24 * 68; i += 256) {
        int r = i / 68, c = i - r * 68;
        t2[i] = h5(&b1[r * 72 + c]);
    }
    __syncthreads();
    for (int i = tid; i < 20 * 68; i += 256) {
        int r = i / 68, c = i - r * 68;
        b2[i] = v5<68>(&t2[r * 68 + c]);
    }
    __syncthreads();
    for (int i = tid; i < 20 * 64; i += 256) {
        int r = i / 64, c = i - r * 64;
        t3[i] = h5(&b2[r * 68 + c]);
    }
    __syncthreads();

    int b = img / 3, cc = img % 3;
    float* lpo = dout + (size_t)(b*87 + cc*29 + 28) * HW;
    for (int i = tid; i < 1024; i += 256) {
        int ty = i >> 6, tx = i & 63;
        size_t pix = (size_t)(y0+ty)*W + x0 + tx;
        size_t go = pbase + pix;
        float l1 = b1[(ty+4)*72 + tx + 4];
        float l2 = b2[(ty+2)*68 + tx + 2];
        g_bp[1][go] = l1 - l2;
        float l3 = v5<64>(&t3[ty * 64 + tx]);
        g_bp[2][go] = l2 - l3;
        lpo[pix] = l3;
    }
}

// =====================================================================
// Directional 15x15 conv — template machinery (antisym + skip + fma-diff)
// =====================================================================
#define DT_W 64
#define DCOLS 78
#define DSTR  84       // 84%32=20 -> 8 consecutive rows hit distinct banks
#define UDROWS 46      // shared tile rows for 64x32 tiles (max of all scales)

template<int S, int D0, int ND, int NDIR, int I, int DD = 0>
struct AnySig {
    static constexpr float w = Filt<S, D0+DD, ND>::f.w[I];
    static constexpr bool v = (w > TAU || w < -TAU) || AnySig<S, D0, ND, NDIR, I, DD+1>::v;
};
template<int S, int D0, int ND, int NDIR, int I>
struct AnySig<S, D0, ND, NDIR, I, NDIR> { static constexpr bool v = false; };

template<int S, int D0, int ND, int NDIR, int NPX, int I, int DD = 0>
struct FmaN {
    static __device__ __forceinline__ void run(const float (&d)[NPX], float (&acc)[NDIR][NPX]) {
        constexpr float w = Filt<S, D0+DD, ND>::f.w[I];
        if constexpr (w > TAU || w < -TAU) {
            #pragma unroll
            for (int t = 0; t < NPX; t++)
                acc[DD][t] = fmaf(d[t], w, acc[DD][t]);
        }
        FmaN<S, D0, ND, NDIR, NPX, I, DD+1>::run(d, acc);
    }
};
template<int S, int D0, int ND, int NDIR, int NPX, int I>
struct FmaN<S, D0, ND, NDIR, NPX, I, NDIR> {
    static __device__ __forceinline__ void run(const float (&)[NPX], float (&)[NDIR][NPX]) {}
};

template<int NPX> struct RowLen { static constexpr int v = (NPX == 4) ? 20 : 16; };

template<int NPX>
__device__ __forceinline__ void load_row(const float* p, float (&r)[RowLen<NPX>::v]) {
    if constexpr (NPX == 4) {
        const float4* rp = (const float4*)p;
        #pragma unroll
        for (int q = 0; q < 5; q++) {
            float4 v = rp[q];
            r[4*q] = v.x; r[4*q+1] = v.y; r[4*q+2] = v.z; r[4*q+3] = v.w;
        }
    } else {
        const float2* rp = (const float2*)p;
        #pragma unroll
        for (int q = 0; q < 8; q++) {
            float2 v = rp[q];
            r[2*q] = v.x; r[2*q+1] = v.y;
        }
    }
}

template<int S, int D0, int ND, int NDIR, int NPX, int KY, int KX>
struct KxP {
    static __device__ __forceinline__ void run(const float (&rA)[RowLen<NPX>::v],
                                               const float (&rB)[RowLen<NPX>::v],
                                               float (&acc)[NDIR][NPX]) {
        if constexpr (AnySig<S, D0, ND, NDIR, KY*15 + KX>::v) {
            float d[NPX];
            #pragma unroll
            for (int t = 0; t < NPX; t++)
                d[t] = fsub_fma(rA[KX + t], rB[14 - KX + t]);
            FmaN<S, D0, ND, NDIR, NPX, KY*15 + KX>::run(d, acc);
        }
        KxP<S, D0, ND, NDIR, NPX, KY, KX+1>::run(rA, rB, acc);
    }
};
template<int S, int D0, int ND, int NDIR, int NPX, int KY>
struct KxP<S, D0, ND, NDIR, NPX, KY, 15> {
    static __device__ __forceinline__ void run(const float (&)[RowLen<NPX>::v],
                                               const float (&)[RowLen<NPX>::v],
                                               float (&)[NDIR][NPX]) {}
};

template<int S, int D0, int ND, int NDIR, int NPX, int KX>
struct KxC {
    static __device__ __forceinline__ void run(const float (&r)[RowLen<NPX>::v],
                                               float (&acc)[NDIR][NPX]) {
        if constexpr (AnySig<S, D0, ND, NDIR, 7*15 + KX>::v) {
            float d[NPX];
            #pragma unroll
            for (int t = 0; t < NPX; t++)
                d[t] = fsub_fma(r[KX + t], r[14 - KX + t]);
            FmaN<S, D0, ND, NDIR, NPX, 7*15 + KX>::run(d, acc);
        }
        KxC<S, D0, ND, NDIR, NPX, KX+1>::run(r, acc);
    }
};
template<int S, int D0, int ND, int NDIR, int NPX>
struct KxC<S, D0, ND, NDIR, NPX, 7> {
    static __device__ __forceinline__ void run(const float (&)[RowLen<NPX>::v],
                                               float (&)[NDIR][NPX]) {}
};

template<int S, int D0, int ND, int NDIR, int NPX, int KY>
struct RowP {
    static __device__ __forceinline__ void run(const float* sp, float (&acc)[NDIR][NPX]) {
        float rA[RowLen<NPX>::v], rB[RowLen<NPX>::v];
        load_row<NPX>(sp + KY * DSTR, rA);
        load_row<NPX>(sp + (14 - KY) * DSTR, rB);
        KxP<S, D0, ND, NDIR, NPX, KY, 0>::run(rA, rB, acc);
        RowP<S, D0, ND, NDIR, NPX, KY+1>::run(sp, acc);
    }
};
template<int S, int D0, int ND, int NDIR, int NPX>
struct RowP<S, D0, ND, NDIR, NPX, 7> {
    static __device__ __forceinline__ void run(const float* sp, float (&acc)[NDIR][NPX]) {
        float r[RowLen<NPX>::v];
        load_row<NPX>(sp + 7 * DSTR, r);
        KxC<S, D0, ND, NDIR, NPX, 0>::run(r, acc);
    }
};

// one scale's work on the shared 64x32 tile; NT=512 threads
template<int S, int D0, int ND, int NDIR, int CH0, int NPX, int NPASS>
__device__ __forceinline__ void dir_impl(float* __restrict__ dout, float* s_in,
                                         int img, int x0, int y0, int tid) {
    constexpr int TILE_H = 32;
    constexpr int DROWS = TILE_H + 14;
    constexpr int PASS_H = TILE_H / NPASS;

    const float* bp = g_bp[S] + (size_t)img * HW;

    for (int i = tid; i < DROWS * DCOLS; i += 512) {
        int r = i / DCOLS, c = i - r * DCOLS;
        int gy = reflect_idx(y0 + r - 7, H);
        int gx = reflect_idx(x0 + c - 7, W);
        s_in[r * DSTR + c] = __ldg(bp + gy * W + gx);
    }
    __syncthreads();

    int sub = tid & 7;
    int ty0, xg;
    if constexpr (NPX == 4) {
        xg = (tid >> 3) & 15;          // 16 x-groups of 4 px
        ty0 = (tid >> 7) * 8 + sub;    // 0..31
    } else {
        xg = (tid >> 3) & 31;          // 32 x-groups of 2 px
        ty0 = (tid >> 8) * 8 + sub;    // 0..15
    }

    int b = img / 3, c = img % 3;

    #pragma unroll 1
    for (int p = 0; p < NPASS; p++) {
        int ty = ty0 + p * PASS_H;
        const float* sp = &s_in[ty * DSTR + xg * NPX];

        float acc[NDIR][NPX];
        #pragma unroll
        for (int d = 0; d < NDIR; d++)
            #pragma unroll
            for (int t = 0; t < NPX; t++) acc[d][t] = 0.f;

        RowP<S, D0, ND, NDIR, NPX, 0>::run(sp, acc);

        size_t outoff = (size_t)(y0 + ty) * W + x0 + xg * NPX;
        float* obase = dout + (size_t)(b*87 + c*29 + CH0) * HW + outoff;
        #pragma unroll
        for (int d = 0; d < NDIR; d++) {
            float* op = obase + (size_t)d * HW;
            if constexpr (NPX == 4)
                *(float4*)op = make_float4(acc[d][0], acc[d][1], acc[d][2], acc[d][3]);
            else
                *(float2*)op = make_float2(acc[d][0], acc[d][1]);
        }
    }
}

// single launch for all scales: blockIdx.z = img*3 + scale
__global__ __launch_bounds__(512) void dir_uber_kernel(float* __restrict__ dout) {
    __shared__ float s_in[UDROWS * DSTR];

    int z = blockIdx.z;
    int img = z / 3;
    int sid = z - img * 3;
    int x0 = blockIdx.x * DT_W;
    int y0 = blockIdx.y * 32;
    int tid = threadIdx.x;

    if (sid == 0) {
        dir_impl<0, 0, 4, 4, 0, 4, 1>(dout, s_in, img, x0, y0, tid);
    } else if (sid == 1) {
        dir_impl<1, 0, 8, 8, 4, 4, 1>(dout, s_in, img, x0, y0, tid);
    } else {
        dir_impl<2, 0, 16, 16, 12, 2, 2>(dout, s_in, img, x0, y0, tid);
    }
}

// ---------------- launch ----------------
extern "C" void kernel_launch(void* const* d_in, const int* in_sizes, int n_in,
                              void* d_out, int out_size) {
    const float* x = (const float*)d_in[0];
    float* out = (float*)d_out;

    dim3 grid16(W / 64, H / 16, NIMG);        // 6 x 24 x 24
    lp_fused_kernel<<<grid16, 256>>>(x, out);

    dim3 gridU(W / 64, H / 32, NIMG * 3);     // 6 x 12 x 72
    dir_uber_kernel<<<gridU, 512>>>(out);
}

// round 17
// speedup vs baseline: 1.0361x; 1.0361x over previous
#include <cuda_runtime.h>
#include <math.h>

#define W 384
#define H 384
#define HW (W*H)
#define NIMG 24

#define TAU 2e-4f

// ---------------- scratch (no allocations allowed) ----------------
__device__ float g_bp[3][NIMG*HW];        // bandpasses

// =====================================================================
// Compile-time double-precision math (matches numpy float64 to ~1e-15)
// =====================================================================
constexpr double PI_ = 3.14159265358979323846264338327950288;

constexpr double cexp(double x) {
    const double LN2 = 0.69314718055994530941723212145817657;
    int n = (int)(x / LN2 + (x >= 0 ? 0.5 : -0.5));
    double r = x - (double)n * LN2;
    double t = 1.0, term = 1.0;
    for (int i = 1; i <= 22; i++) { term *= r / (double)i; t += term; }
    double s = 1.0;
    if (n >= 0) for (int i = 0; i < n; i++)  s *= 2.0;
    else        for (int i = 0; i < -n; i++) s *= 0.5;
    return t * s;
}
constexpr double ccos(double x) {
    double t = x; bool neg = false;
    if (t > PI_ * 0.5) { t = PI_ - t; neg = true; }
    double t2 = t*t, term = 1.0, s = 1.0;
    for (int i = 1; i <= 16; i++) { term *= -t2 / (double)((2*i-1)*(2*i)); s += term; }
    return neg ? -s : s;
}
constexpr double csin(double x) {
    double t = x;
    if (t > PI_ * 0.5) t = PI_ - t;
    double t2 = t*t, term = t, s = t;
    for (int i = 1; i <= 16; i++) { term *= -t2 / (double)((2*i)*(2*i+1)); s += term; }
    return s;
}
constexpr double csqrt(double x) {
    if (x <= 0.0) return 0.0;
    double y = (x > 1.0) ? x : 1.0;
    for (int i = 0; i < 80; i++) y = 0.5 * (y + x / y);
    return y;
}

// ---------------- oriented 15x15 filters, computed at compile time ----------------
struct F225 { float w[225]; };

constexpr F225 make_filt(int s, int d, int nd) {
    double scale = (double)(s + 1);
    double sx = 2.0 * scale, sy = 0.5 * scale;
    double ang = PI_ * (double)d / (double)nd;
    double ca = ccos(ang), sa = csin(ang);
    double k[225] = {};
    double sum = 0.0;
    for (int i = 0; i < 15; i++) {
        for (int j = 0; j < 15; j++) {
            double X = (double)(j - 7), Y = (double)(i - 7);
            double Xr = X * ca - Y * sa;
            double Yr = X * sa + Y * ca;
            double v = cexp(-0.5 * (Xr*Xr/(sx*sx) + Yr*Yr/(sy*sy))) * Xr / (sx*sx);
            k[i*15 + j] = v;
            sum += v;
        }
    }
    double mean = sum / 225.0;
    double nr = 0.0;
    for (int i = 0; i < 225; i++) { k[i] -= mean; nr += k[i]*k[i]; }
    nr = csqrt(nr);
    double inv = (nr > 1e-6) ? 1.0 / nr : 1.0;
    F225 f{};
    for (int i = 0; i < 225; i++) f.w[i] = (float)(k[i] * inv);
    return f;
}

template<int S, int D, int ND>
struct Filt { static constexpr F225 f = make_filt(S, D, ND); };
template<int S, int D, int ND> constexpr F225 Filt<S, D, ND>::f;

// ---------------- separable 5-tap gaussian at compile time ----------------
struct F5 { float h[5]; float v[5]; };
constexpr F5 make_k1() {
    double g[5] = {}; double s1 = 0.0;
    for (int i = 0; i < 5; i++) { double a = (double)(i - 2); g[i] = cexp(-0.5*a*a); s1 += g[i]; }
    double k1[5] = {};
    for (int i = 0; i < 5; i++) k1[i] = g[i] / s1;
    double s2 = 0.0;
    for (int i = 0; i < 5; i++)
        for (int j = 0; j < 5; j++) s2 += k1[i]*k1[j];
    F5 f{};
    for (int i = 0; i < 5; i++) { f.h[i] = (float)k1[i]; f.v[i] = (float)(k1[i] / s2); }
    return f;
}
template<int DUMMY>
struct K1T { static constexpr F5 f = make_k1(); };
template<int DUMMY> constexpr F5 K1T<DUMMY>::f;

__device__ __forceinline__ int reflect_idx(int i, int n) {
    if (i < 0) return -i;
    if (i >= n) return 2*n - 2 - i;
    return i;
}

__device__ __forceinline__ float fsub_fma(float a, float b) {
    return fmaf(b, -1.0f, a);
}

// 5-tap horiz / vert with immediate weights
template<int I>
struct H5t {
    static __device__ __forceinline__ void run(const float* s, float& a) {
        constexpr float w = K1T<0>::f.h[I];
        a = fmaf(s[I], w, a);
        H5t<I+1>::run(s, a);
    }
};
template<> struct H5t<5> { static __device__ __forceinline__ void run(const float*, float&) {} };
__device__ __forceinline__ float h5(const float* s) { float a = 0.f; H5t<0>::run(s, a); return a; }

template<int STR, int I>
struct V5t {
    static __device__ __forceinline__ void run(const float* s, float& a) {
        constexpr float w = K1T<0>::f.v[I];
        a = fmaf(s[I*STR], w, a);
        V5t<STR, I+1>::run(s, a);
    }
};
template<int STR> struct V5t<STR, 5> { static __device__ __forceinline__ void run(const float*, float&) {} };
template<int STR>
__device__ __forceinline__ float v5(const float* s) { float a = 0.f; V5t<STR,0>::run(s, a); return a; }

// =====================================================================
// Fused 3-stage Laplacian pyramid, separable 5-tap passes.
// =====================================================================
#define B0S 76

__global__ __launch_bounds__(256) void lp_fused_kernel(const float* __restrict__ xin,
                                                       float* __restrict__ dout) {
    __shared__ float b0[28 * B0S];
    __shared__ float t1[28 * 72];
    __shared__ float b1[24 * 72];
    __shared__ float t2[24 * 68];
    __shared__ float b2[20 * 68];
    __shared__ float t3[20 * 64];

    int img = blockIdx.z;
    int x0 = blockIdx.x * 64;
    int y0 = blockIdx.y * 16;
    const float* base = xin + (size_t)img * HW;
    int tid = threadIdx.x;

    for (int i = tid; i < 28 * B0S; i += 256) {
        int r = i / B0S, c = i - r * B0S;
        int gy = reflect_idx(y0 - 6 + r, H);
        int gx = reflect_idx(x0 - 6 + c, W);
        b0[i] = __ldg(base + gy * W + gx);
    }
    __syncthreads();

    for (int i = tid; i < 28 * 72; i += 256) {
        int r = i / 72, c = i - r * 72;
        t1[i] = h5(&b0[r * B0S + c]);
    }
    __syncthreads();
    for (int i = tid; i < 24 * 72; i += 256) {
        int r = i / 72, c = i - r * 72;
        b1[i] = v5<72>(&t1[r * 72 + c]);
    }
    __syncthreads();

    size_t pbase = (size_t)img * HW;
    {
        int i = tid;
        int ty = i >> 4, tx4 = (i & 15) * 4;
        float v[4];
        #pragma unroll
        for (int t = 0; t < 4; t++)
            v[t] = b0[(ty+6)*B0S + tx4 + t + 6] - b1[(ty+4)*72 + tx4 + t + 4];
        *(float4*)&g_bp[0][pbase + (size_t)(y0+ty)*W + x0 + tx4] =
            make_float4(v[0], v[1], v[2], v[3]);
    }
    for (int i = tid; i < 24 * 68; i += 256) {
        int r = i / 68, c = i - r * 68;
        t2[i] = h5(&b1[r * 72 + c]);
    }
    __syncthreads();
    for (int i = tid; i < 20 * 68; i += 256) {
        int r = i / 68, c = i - r * 68;
        b2[i] = v5<68>(&t2[r * 68 + c]);
    }
    __syncthreads();
    for (int i = tid; i < 20 * 64; i += 256) {
        int r = i / 64, c = i - r * 64;
        t3[i] = h5(&b2[r * 68 + c]);
    }
    __syncthreads();

    int b = img / 3, cc = img % 3;
    float* lpo = dout + (size_t)(b*87 + cc*29 + 28) * HW;
    for (int i = tid; i < 1024; i += 256) {
        int ty = i >> 6, tx = i & 63;
        size_t pix = (size_t)(y0+ty)*W + x0 + tx;
        size_t go = pbase + pix;
        float l1 = b1[(ty+4)*72 + tx + 4];
        float l2 = b2[(ty+2)*68 + tx + 2];
        g_bp[1][go] = l1 - l2;
        float l3 = v5<64>(&t3[ty * 64 + tx]);
        g_bp[2][go] = l2 - l3;
        lpo[pix] = l3;
    }
}

// =====================================================================
// Directional 15x15 conv — template machinery (antisym + skip + fma-diff)
// =====================================================================
#define DT_W 64
#define DCOLS 78
#define DSTR  84       // 84%32=20 -> 8 consecutive rows hit distinct banks
#define UDROWS 46      // shared tile rows for 64x32 tiles (max of all scales)

template<int S, int D0, int ND, int NDIR, int I, int DD = 0>
struct AnySig {
    static constexpr float w = Filt<S, D0+DD, ND>::f.w[I];
    static constexpr bool v = (w > TAU || w < -TAU) || AnySig<S, D0, ND, NDIR, I, DD+1>::v;
};
template<int S, int D0, int ND, int NDIR, int I>
struct AnySig<S, D0, ND, NDIR, I, NDIR> { static constexpr bool v = false; };

template<int S, int D0, int ND, int NDIR, int NPX, int I, int DD = 0>
struct FmaN {
    static __device__ __forceinline__ void run(const float (&d)[NPX], float (&acc)[NDIR][NPX]) {
        constexpr float w = Filt<S, D0+DD, ND>::f.w[I];
        if constexpr (w > TAU || w < -TAU) {
            #pragma unroll
            for (int t = 0; t < NPX; t++)
                acc[DD][t] = fmaf(d[t], w, acc[DD][t]);
        }
        FmaN<S, D0, ND, NDIR, NPX, I, DD+1>::run(d, acc);
    }
};
template<int S, int D0, int ND, int NDIR, int NPX, int I>
struct FmaN<S, D0, ND, NDIR, NPX, I, NDIR> {
    static __device__ __forceinline__ void run(const float (&)[NPX], float (&)[NDIR][NPX]) {}
};

template<int NPX> struct RowLen { static constexpr int v = (NPX == 4) ? 20 : 16; };

template<int NPX>
__device__ __forceinline__ void load_row(const float* p, float (&r)[RowLen<NPX>::v]) {
    if constexpr (NPX == 4) {
        const float4* rp = (const float4*)p;
        #pragma unroll
        for (int q = 0; q < 5; q++) {
            float4 v = rp[q];
            r[4*q] = v.x; r[4*q+1] = v.y; r[4*q+2] = v.z; r[4*q+3] = v.w;
        }
    } else {
        const float2* rp = (const float2*)p;
        #pragma unroll
        for (int q = 0; q < 8; q++) {
            float2 v = rp[q];
            r[2*q] = v.x; r[2*q+1] = v.y;
        }
    }
}

template<int S, int D0, int ND, int NDIR, int NPX, int KY, int KX>
struct KxP {
    static __device__ __forceinline__ void run(const float (&rA)[RowLen<NPX>::v],
                                               const float (&rB)[RowLen<NPX>::v],
                                               float (&acc)[NDIR][NPX]) {
        if constexpr (AnySig<S, D0, ND, NDIR, KY*15 + KX>::v) {
            float d[NPX];
            #pragma unroll
            for (int t = 0; t < NPX; t++)
                d[t] = fsub_fma(rA[KX + t], rB[14 - KX + t]);
            FmaN<S, D0, ND, NDIR, NPX, KY*15 + KX>::run(d, acc);
        }
        KxP<S, D0, ND, NDIR, NPX, KY, KX+1>::run(rA, rB, acc);
    }
};
template<int S, int D0, int ND, int NDIR, int NPX, int KY>
struct KxP<S, D0, ND, NDIR, NPX, KY, 15> {
    static __device__ __forceinline__ void run(const float (&)[RowLen<NPX>::v],
                                               const float (&)[RowLen<NPX>::v],
                                               float (&)[NDIR][NPX]) {}
};

template<int S, int D0, int ND, int NDIR, int NPX, int KX>
struct KxC {
    static __device__ __forceinline__ void run(const float (&r)[RowLen<NPX>::v],
                                               float (&acc)[NDIR][NPX]) {
        if constexpr (AnySig<S, D0, ND, NDIR, 7*15 + KX>::v) {
            float d[NPX];
            #pragma unroll
            for (int t = 0; t < NPX; t++)
                d[t] = fsub_fma(r[KX + t], r[14 - KX + t]);
            FmaN<S, D0, ND, NDIR, NPX, 7*15 + KX>::run(d, acc);
        }
        KxC<S, D0, ND, NDIR, NPX, KX+1>::run(r, acc);
    }
};
template<int S, int D0, int ND, int NDIR, int NPX>
struct KxC<S, D0, ND, NDIR, NPX, 7> {
    static __device__ __forceinline__ void run(const float (&)[RowLen<NPX>::v],
                                               float (&)[NDIR][NPX]) {}
};

template<int S, int D0, int ND, int NDIR, int NPX, int KY>
struct RowP {
    static __device__ __forceinline__ void run(const float* sp, float (&acc)[NDIR][NPX]) {
        float rA[RowLen<NPX>::v], rB[RowLen<NPX>::v];
        load_row<NPX>(sp + KY * DSTR, rA);
        load_row<NPX>(sp + (14 - KY) * DSTR, rB);
        KxP<S, D0, ND, NDIR, NPX, KY, 0>::run(rA, rB, acc);
        RowP<S, D0, ND, NDIR, NPX, KY+1>::run(sp, acc);
    }
};
template<int S, int D0, int ND, int NDIR, int NPX>
struct RowP<S, D0, ND, NDIR, NPX, 7> {
    static __device__ __forceinline__ void run(const float* sp, float (&acc)[NDIR][NPX]) {
        float r[RowLen<NPX>::v];
        load_row<NPX>(sp + 7 * DSTR, r);
        KxC<S, D0, ND, NDIR, NPX, 0>::run(r, acc);
    }
};

// one scale's work on the shared 64x32 tile; NT=512 threads
template<int S, int D0, int ND, int NDIR, int CH0, int NPX, int NPASS>
__device__ __forceinline__ void dir_impl(float* __restrict__ dout, float* s_in,
                                         int img, int x0, int y0, int tid) {
    constexpr int TILE_H = 32;
    constexpr int DROWS = TILE_H + 14;
    constexpr int PASS_H = TILE_H / NPASS;

    const float* bp = g_bp[S] + (size_t)img * HW;

    for (int i = tid; i < DROWS * DCOLS; i += 512) {
        int r = i / DCOLS, c = i - r * DCOLS;
        int gy = reflect_idx(y0 + r - 7, H);
        int gx = reflect_idx(x0 + c - 7, W);
        s_in[r * DSTR + c] = __ldg(bp + gy * W + gx);
    }
    __syncthreads();

    int sub = tid & 7;
    int ty0, xg;
    if constexpr (NPX == 4) {
        xg = (tid >> 3) & 15;          // 16 x-groups of 4 px
        ty0 = (tid >> 7) * 8 + sub;    // 0..31
    } else {
        xg = (tid >> 3) & 31;          // 32 x-groups of 2 px
        ty0 = (tid >> 8) * 8 + sub;    // 0..15
    }

    int b = img / 3, c = img % 3;

    #pragma unroll 1
    for (int p = 0; p < NPASS; p++) {
        int ty = ty0 + p * PASS_H;
        const float* sp = &s_in[ty * DSTR + xg * NPX];

        float acc[NDIR][NPX];
        #pragma unroll
        for (int d = 0; d < NDIR; d++)
            #pragma unroll
            for (int t = 0; t < NPX; t++) acc[d][t] = 0.f;

        RowP<S, D0, ND, NDIR, NPX, 0>::run(sp, acc);

        size_t outoff = (size_t)(y0 + ty) * W + x0 + xg * NPX;
        float* obase = dout + (size_t)(b*87 + c*29 + CH0) * HW + outoff;
        #pragma unroll
        for (int d = 0; d < NDIR; d++) {
            float* op = obase + (size_t)d * HW;
            if constexpr (NPX == 4)
                *(float4*)op = make_float4(acc[d][0], acc[d][1], acc[d][2], acc[d][3]);
            else
                *(float2*)op = make_float2(acc[d][0], acc[d][1]);
        }
    }
}

// single launch for all scales — SCALE-MAJOR z ordering so contiguous
// launch phases run the same unrolled body (I$ stays warm):
//   z in [0,24)  -> scale 0,  z in [24,48) -> scale 1,  z in [48,72) -> scale 2
__global__ __launch_bounds__(512) void dir_uber_kernel(float* __restrict__ dout) {
    __shared__ float s_in[UDROWS * DSTR];

    int z = blockIdx.z;
    int sid = z / NIMG;
    int img = z - sid * NIMG;
    int x0 = blockIdx.x * DT_W;
    int y0 = blockIdx.y * 32;
    int tid = threadIdx.x;

    if (sid == 0) {
        dir_impl<0, 0, 4, 4, 0, 4, 1>(dout, s_in, img, x0, y0, tid);
    } else if (sid == 1) {
        dir_impl<1, 0, 8, 8, 4, 4, 1>(dout, s_in, img, x0, y0, tid);
    } else {
        dir_impl<2, 0, 16, 16, 12, 2, 2>(dout, s_in, img, x0, y0, tid);
    }
}

// ---------------- launch ----------------
extern "C" void kernel_launch(void* const* d_in, const int* in_sizes, int n_in,
                              void* d_out, int out_size) {
    const float* x = (const float*)d_in[0];
    float* out = (float*)d_out;

    dim3 grid16(W / 64, H / 16, NIMG);        // 6 x 24 x 24
    lp_fused_kernel<<<grid16, 256>>>(x, out);

    dim3 gridU(W / 64, H / 32, NIMG * 3);     // 6 x 12 x 72
    dir_uber_kernel<<<gridU, 512>>>(out);
}